// round 4
// baseline (speedup 1.0000x reference)
#include <cuda_runtime.h>
#include <cuda_bf16.h>
#include <math.h>

#define B_SZ   1024
#define C_SZ   100000
#define D_SZ   256
#define EPSV   1e-12f
#define SCALAR 30.0f
#define MOM    0.5f

// out layout: predicts | targets(as float) | new_weight
#define OUT_PRED 0
#define OUT_TGT  (B_SZ * C_SZ)                 // 102,400,000
#define OUT_W    (B_SZ * C_SZ + B_SZ)          // 102,401,024

// scratch
__device__ float g_xnorm[B_SZ * D_SZ];
__device__ float g_winv[C_SZ];

// ---------------------------------------------------------------------------
// 1) normalize inputs: one block (256 threads) per row
// ---------------------------------------------------------------------------
__global__ void normalize_x_kernel(const float* __restrict__ x) {
    int b = blockIdx.x;
    int t = threadIdx.x;
    float v = x[b * D_SZ + t];
    float ss = v * v;
    // block reduce
    __shared__ float sm[8];
    for (int o = 16; o; o >>= 1) ss += __shfl_xor_sync(0xFFFFFFFFu, ss, o);
    int w = t >> 5, l = t & 31;
    if (l == 0) sm[w] = ss;
    __syncthreads();
    if (w == 0) {
        float s = (l < 8) ? sm[l] : 0.0f;
        for (int o = 4; o; o >>= 1) s += __shfl_xor_sync(0xFFFFFFFFu, s, o);
        if (l == 0) sm[0] = s;
    }
    __syncthreads();
    float nrm = sqrtf(sm[0]);
    g_xnorm[b * D_SZ + t] = v / fmaxf(nrm, EPSV);
}

// ---------------------------------------------------------------------------
// 2) per-class scale: winv[c] = SCALAR / max(||w_c||, eps). One warp per class.
// ---------------------------------------------------------------------------
__global__ void winv_kernel(const float* __restrict__ w) {
    int warp = (blockIdx.x * blockDim.x + threadIdx.x) >> 5;
    int lane = threadIdx.x & 31;
    if (warp >= C_SZ) return;
    const float* row = w + (size_t)warp * D_SZ + lane * 8;
    float4 a = *(const float4*)(row);
    float4 b = *(const float4*)(row + 4);
    float ss = a.x*a.x + a.y*a.y + a.z*a.z + a.w*a.w
             + b.x*b.x + b.y*b.y + b.z*b.z + b.w*b.w;
    for (int o = 16; o; o >>= 1) ss += __shfl_xor_sync(0xFFFFFFFFu, ss, o);
    if (lane == 0) g_winv[warp] = SCALAR / fmaxf(sqrtf(ss), EPSV);
}

// ---------------------------------------------------------------------------
// 3) copy raw weight into the output new_weight region (float4 grid-stride)
// ---------------------------------------------------------------------------
__global__ void copy_w_kernel(const float* __restrict__ w, float* __restrict__ dst) {
    size_t i = (size_t)blockIdx.x * blockDim.x + threadIdx.x;
    size_t n4 = (size_t)C_SZ * D_SZ / 4;
    if (i < n4) ((float4*)dst)[i] = ((const float4*)w)[i];
}

// ---------------------------------------------------------------------------
// 4) targets -> float in output
// ---------------------------------------------------------------------------
__global__ void targets_out_kernel(const int* __restrict__ tgt, float* __restrict__ dst) {
    int i = blockIdx.x * blockDim.x + threadIdx.x;
    if (i < B_SZ) dst[i] = (float)tgt[i];
}

// ---------------------------------------------------------------------------
// 5) sequential momentum update of new_weight rows (exact batch order).
//    One block per sample; only the first occurrence of a class does the work,
//    replaying every later duplicate in order.
// ---------------------------------------------------------------------------
__global__ void seq_update_kernel(const int* __restrict__ tgt, float* __restrict__ wout) {
    int i = blockIdx.x;
    int t = threadIdx.x;
    int cls = tgt[i];

    __shared__ int first;
    __shared__ float sm[9];
    if (t == 0) first = 1;
    __syncthreads();
    for (int j = t; j < i; j += 256)
        if (tgt[j] == cls) first = 0;
    __syncthreads();
    if (!first) return;

    float v = wout[(size_t)cls * D_SZ + t];
    for (int j = i; j < B_SZ; ++j) {
        if (tgt[j] != cls) continue;   // uniform branch across block
        v = MOM * v + (1.0f - MOM) * g_xnorm[j * D_SZ + t];
        float ss = v * v;
        for (int o = 16; o; o >>= 1) ss += __shfl_xor_sync(0xFFFFFFFFu, ss, o);
        int w = t >> 5, l = t & 31;
        if (l == 0) sm[w] = ss;
        __syncthreads();
        if (t == 0) {
            float s = 0.0f;
            for (int k = 0; k < 8; ++k) s += sm[k];
            sm[8] = s;
        }
        __syncthreads();
        float nrm = sqrtf(sm[8]);
        v = v / fmaxf(nrm, EPSV);
        __syncthreads();
    }
    wout[(size_t)cls * D_SZ + t] = v;
}

// ---------------------------------------------------------------------------
// 6) GEMM: predicts[b][c] = dot(xnorm[b], w[c]) * winv[c]
//    Tiles: 128 (batch) x 64 (class) x 16 (k). 256 threads, 8x4 per thread.
// ---------------------------------------------------------------------------
#define TB 128
#define TC 64
#define TK 16

__global__ __launch_bounds__(256) void gemm_kernel(
    const float* __restrict__ w, float* __restrict__ out)
{
    __shared__ float As[TK][TB];
    __shared__ float Bs[TK][TC + 4];

    int c0 = blockIdx.x * TC;
    int b0 = blockIdx.y * TB;
    int t  = threadIdx.x;
    int tx = t & 15;        // class sub (4 each)
    int ty = t >> 4;        // batch sub (8 each)

    // A load mapping: row ar (0..127), k-half ah (0/1, 8 floats each)
    int ar = t & 127, ah = t >> 7;
    // B load mapping: row br (0..63), k-quarter bq (0..3, 4 floats each)
    int br = t & 63, bq = t >> 6;

    const float* aptr = g_xnorm + (size_t)(b0 + ar) * D_SZ + ah * 8;
    bool bvalid = (c0 + br) < C_SZ;
    const float* bptr = w + (size_t)(c0 + br) * D_SZ + bq * 4;

    float acc[8][4];
#pragma unroll
    for (int i = 0; i < 8; ++i)
#pragma unroll
        for (int j = 0; j < 4; ++j) acc[i][j] = 0.0f;

    for (int k0 = 0; k0 < D_SZ; k0 += TK) {
        float4 a0 = *(const float4*)(aptr + k0);
        float4 a1 = *(const float4*)(aptr + k0 + 4);
        float4 bv = bvalid ? *(const float4*)(bptr + k0)
                           : make_float4(0.f, 0.f, 0.f, 0.f);
        __syncthreads();
        As[ah * 8 + 0][ar] = a0.x;
        As[ah * 8 + 1][ar] = a0.y;
        As[ah * 8 + 2][ar] = a0.z;
        As[ah * 8 + 3][ar] = a0.w;
        As[ah * 8 + 4][ar] = a1.x;
        As[ah * 8 + 5][ar] = a1.y;
        As[ah * 8 + 6][ar] = a1.z;
        As[ah * 8 + 7][ar] = a1.w;
        Bs[bq * 4 + 0][br] = bv.x;
        Bs[bq * 4 + 1][br] = bv.y;
        Bs[bq * 4 + 2][br] = bv.z;
        Bs[bq * 4 + 3][br] = bv.w;
        __syncthreads();

#pragma unroll
        for (int kk = 0; kk < TK; ++kk) {
            float4 a0c = *(const float4*)&As[kk][ty * 8];
            float4 a1c = *(const float4*)&As[kk][ty * 8 + 4];
            float4 bc  = *(const float4*)&Bs[kk][tx * 4];
            float av[8] = {a0c.x, a0c.y, a0c.z, a0c.w, a1c.x, a1c.y, a1c.z, a1c.w};
            float bvv[4] = {bc.x, bc.y, bc.z, bc.w};
#pragma unroll
            for (int i = 0; i < 8; ++i)
#pragma unroll
                for (int j = 0; j < 4; ++j)
                    acc[i][j] = fmaf(av[i], bvv[j], acc[i][j]);
        }
    }

    // epilogue: scale by winv and store
    int c = c0 + tx * 4;
    float wv[4];
#pragma unroll
    for (int j = 0; j < 4; ++j)
        wv[j] = (c + j < C_SZ) ? g_winv[c + j] : 0.0f;

#pragma unroll
    for (int i = 0; i < 8; ++i) {
        int b = b0 + ty * 8 + i;
        float4 r = make_float4(acc[i][0] * wv[0], acc[i][1] * wv[1],
                               acc[i][2] * wv[2], acc[i][3] * wv[3]);
        float* dst = out + (size_t)b * C_SZ + c;
        if (c + 3 < C_SZ) {
            *(float4*)dst = r;
        } else {
            if (c + 0 < C_SZ) dst[0] = r.x;
            if (c + 1 < C_SZ) dst[1] = r.y;
            if (c + 2 < C_SZ) dst[2] = r.z;
            if (c + 3 < C_SZ) dst[3] = r.w;
        }
    }
}

// ---------------------------------------------------------------------------
extern "C" void kernel_launch(void* const* d_in, const int* in_sizes, int n_in,
                              void* d_out, int out_size) {
    const float* x   = (const float*)d_in[0];
    const int*   tgt = (const int*)d_in[1];
    const float* w   = (const float*)d_in[2];
    float* out = (float*)d_out;

    normalize_x_kernel<<<B_SZ, 256>>>(x);

    winv_kernel<<<(C_SZ * 32 + 255) / 256, 256>>>(w);   // 1 warp per class

    copy_w_kernel<<<(C_SZ * D_SZ / 4 + 255) / 256, 256>>>(w, out + OUT_W);

    targets_out_kernel<<<(B_SZ + 255) / 256, 256>>>(tgt, out + OUT_TGT);

    seq_update_kernel<<<B_SZ, 256>>>(tgt, out + OUT_W);

    dim3 grid((C_SZ + TC - 1) / TC, B_SZ / TB);
    gemm_kernel<<<grid, 256>>>(w, out + OUT_PRED);
}

// round 6
// speedup vs baseline: 2.1915x; 2.1915x over previous
#include <cuda_runtime.h>
#include <cuda_bf16.h>
#include <math.h>
#include <stdint.h>

#define B_SZ   1024
#define C_SZ   100000
#define C_PAD  100096          /* 782 * 128 */
#define D_SZ   256
#define EPSV   1e-12f
#define SCALAR 30.0f
#define MOM    0.5f

// out layout: predicts | targets(as float) | new_weight
#define OUT_PRED 0
#define OUT_TGT  (B_SZ * C_SZ)
#define OUT_W    (B_SZ * C_SZ + B_SZ)

// ---------------- scratch (static device globals; no allocs) ----------------
__device__ float g_xnorm[B_SZ * D_SZ];
__device__ float g_winv[C_PAD];
__device__ __align__(16) __nv_bfloat16 g_xa_hi[B_SZ * D_SZ];
__device__ __align__(16) __nv_bfloat16 g_xa_lo[B_SZ * D_SZ];
__device__ __align__(16) __nv_bfloat16 g_w_hi[(size_t)C_PAD * D_SZ];
__device__ __align__(16) __nv_bfloat16 g_w_lo[(size_t)C_PAD * D_SZ];

// ---------------- PTX helpers (portable: sm_80+ instructions only) ----------
__device__ __forceinline__ uint32_t smem_u32(const void* p) {
    uint32_t a;
    asm("{ .reg .u64 t; cvta.to.shared.u64 t, %1; cvt.u32.u64 %0, t; }" : "=r"(a) : "l"(p));
    return a;
}
__device__ __forceinline__ void cpa16(uint32_t dst, const void* src) {
    asm volatile("cp.async.cg.shared.global [%0], [%1], 16;"
        :: "r"(dst), "l"((unsigned long long)__cvta_generic_to_global(src)) : "memory");
}
#define CP_COMMIT() asm volatile("cp.async.commit_group;" ::: "memory")
#define CP_WAIT(n)  asm volatile("cp.async.wait_group %0;" :: "n"(n) : "memory")

__device__ __forceinline__ void ldsm_x4(uint32_t* r, uint32_t addr) {
    asm volatile("ldmatrix.sync.aligned.m8n8.x4.shared.b16 {%0,%1,%2,%3}, [%4];"
        : "=r"(r[0]), "=r"(r[1]), "=r"(r[2]), "=r"(r[3]) : "r"(addr));
}
__device__ __forceinline__ void mma16816(float* c, const uint32_t* a, const uint32_t* b) {
    asm volatile("mma.sync.aligned.m16n8k16.row.col.f32.bf16.bf16.f32 "
        "{%0,%1,%2,%3}, {%4,%5,%6,%7}, {%8,%9}, {%0,%1,%2,%3};"
        : "+f"(c[0]), "+f"(c[1]), "+f"(c[2]), "+f"(c[3])
        : "r"(a[0]), "r"(a[1]), "r"(a[2]), "r"(a[3]), "r"(b[0]), "r"(b[1]));
}

// ---------------------------------------------------------------------------
// 1) normalize inputs + emit bf16 hi/lo split
// ---------------------------------------------------------------------------
__global__ void normalize_x_kernel(const float* __restrict__ x) {
    int b = blockIdx.x;
    int t = threadIdx.x;
    float v = x[b * D_SZ + t];
    float ss = v * v;
    __shared__ float sm[8];
    for (int o = 16; o; o >>= 1) ss += __shfl_xor_sync(0xFFFFFFFFu, ss, o);
    int w = t >> 5, l = t & 31;
    if (l == 0) sm[w] = ss;
    __syncthreads();
    if (w == 0) {
        float s = (l < 8) ? sm[l] : 0.0f;
        for (int o = 4; o; o >>= 1) s += __shfl_xor_sync(0xFFFFFFFFu, s, o);
        if (l == 0) sm[0] = s;
    }
    __syncthreads();
    float nrm = sqrtf(sm[0]);
    float xn = v / fmaxf(nrm, EPSV);
    g_xnorm[b * D_SZ + t] = xn;
    __nv_bfloat16 h = __float2bfloat16(xn);
    __nv_bfloat16 lo = __float2bfloat16(xn - __bfloat162float(h));
    g_xa_hi[b * D_SZ + t] = h;
    g_xa_lo[b * D_SZ + t] = lo;
}

// ---------------------------------------------------------------------------
// 2) per-class scale winv[c] = SCALAR / max(||w_c||, eps); padded -> 0
// ---------------------------------------------------------------------------
__global__ void winv_kernel(const float* __restrict__ w) {
    int warp = (blockIdx.x * blockDim.x + threadIdx.x) >> 5;
    int lane = threadIdx.x & 31;
    if (warp >= C_PAD) return;
    if (warp >= C_SZ) { if (lane == 0) g_winv[warp] = 0.0f; return; }
    const float* row = w + (size_t)warp * D_SZ + lane * 8;
    float4 a = *(const float4*)(row);
    float4 b = *(const float4*)(row + 4);
    float ss = a.x*a.x + a.y*a.y + a.z*a.z + a.w*a.w
             + b.x*b.x + b.y*b.y + b.z*b.z + b.w*b.w;
    for (int o = 16; o; o >>= 1) ss += __shfl_xor_sync(0xFFFFFFFFu, ss, o);
    if (lane == 0) g_winv[warp] = SCALAR / fmaxf(sqrtf(ss), EPSV);
}

// ---------------------------------------------------------------------------
// 3) weight -> bf16 hi/lo split (padded rows zeroed)
// ---------------------------------------------------------------------------
__global__ void convert_w_kernel(const float* __restrict__ w) {
    size_t i = (size_t)blockIdx.x * blockDim.x + threadIdx.x; // 8 elems each
    size_t n = (size_t)C_PAD * D_SZ / 8;
    if (i >= n) return;
    size_t e0 = i * 8;
    __nv_bfloat16 hs[8], ls[8];
    if (e0 < (size_t)C_SZ * D_SZ) {
        float4 a = ((const float4*)(w + e0))[0];
        float4 b = ((const float4*)(w + e0))[1];
        float v[8] = {a.x, a.y, a.z, a.w, b.x, b.y, b.z, b.w};
#pragma unroll
        for (int k = 0; k < 8; ++k) {
            __nv_bfloat16 h = __float2bfloat16(v[k]);
            hs[k] = h;
            ls[k] = __float2bfloat16(v[k] - __bfloat162float(h));
        }
    } else {
#pragma unroll
        for (int k = 0; k < 8; ++k) { hs[k] = __float2bfloat16(0.f); ls[k] = hs[k]; }
    }
    *(uint4*)(g_w_hi + e0) = *(uint4*)hs;
    *(uint4*)(g_w_lo + e0) = *(uint4*)ls;
}

// ---------------------------------------------------------------------------
// 4) copy raw weight into new_weight output region
// ---------------------------------------------------------------------------
__global__ void copy_w_kernel(const float* __restrict__ w, float* __restrict__ dst) {
    size_t i = (size_t)blockIdx.x * blockDim.x + threadIdx.x;
    size_t n4 = (size_t)C_SZ * D_SZ / 4;
    if (i < n4) ((float4*)dst)[i] = ((const float4*)w)[i];
}

// ---------------------------------------------------------------------------
// 5) targets -> float
// ---------------------------------------------------------------------------
__global__ void targets_out_kernel(const int* __restrict__ tgt, float* __restrict__ dst) {
    int i = blockIdx.x * blockDim.x + threadIdx.x;
    if (i < B_SZ) dst[i] = (float)tgt[i];
}

// ---------------------------------------------------------------------------
// 6) sequential momentum update (exact batch order, duplicate-safe)
// ---------------------------------------------------------------------------
__global__ void seq_update_kernel(const int* __restrict__ tgt, float* __restrict__ wout) {
    int i = blockIdx.x;
    int t = threadIdx.x;
    int cls = tgt[i];
    __shared__ int first;
    __shared__ float sm[9];
    if (t == 0) first = 1;
    __syncthreads();
    for (int j = t; j < i; j += 256)
        if (tgt[j] == cls) first = 0;
    __syncthreads();
    if (!first) return;
    float v = wout[(size_t)cls * D_SZ + t];
    for (int j = i; j < B_SZ; ++j) {
        if (tgt[j] != cls) continue;
        v = MOM * v + (1.0f - MOM) * g_xnorm[j * D_SZ + t];
        float ss = v * v;
        for (int o = 16; o; o >>= 1) ss += __shfl_xor_sync(0xFFFFFFFFu, ss, o);
        int w = t >> 5, l = t & 31;
        if (l == 0) sm[w] = ss;
        __syncthreads();
        if (t == 0) {
            float s = 0.0f;
            for (int k = 0; k < 8; ++k) s += sm[k];
            sm[8] = s;
        }
        __syncthreads();
        v = v / fmaxf(sqrtf(sm[8]), EPSV);
        __syncthreads();
    }
    wout[(size_t)cls * D_SZ + t] = v;
}

// ---------------------------------------------------------------------------
// 7) mma.sync bf16 hi/lo GEMM: D[128,128] = (xh+xl)·(wh+wl)^T, 3 products.
//    k-chunk 32, 2-stage cp.async, ldmatrix frags, 8 warps of 64x32.
// ---------------------------------------------------------------------------
#define PITCH       80                        /* bytes per smem row (32 bf16 + pad) */
#define TILE_BYTES  (128 * PITCH)             /* 10240 */
#define OFF_AHI     0
#define OFF_ALO     TILE_BYTES
#define OFF_BHI     (2 * TILE_BYTES)
#define OFF_BLO     (3 * TILE_BYTES)
#define STAGE_BYTES (4 * TILE_BYTES)          /* 40960 */
#define SMEM_GEMM   (2 * STAGE_BYTES)         /* 81920 */

__device__ __forceinline__ void load_chunk(uint32_t stage, int kc, int b0, int c0, int tid) {
    int row = tid >> 1;                 // 0..127
    int s0  = (tid & 1) * 2;            // seg 0 or 2 (each seg = 16B = 8 bf16)
#pragma unroll
    for (int i = 0; i < 2; ++i) {
        int s = s0 + i;
        uint32_t so = (uint32_t)(row * PITCH + s * 16);
        size_t gk = (size_t)kc * 32 + s * 8;
        cpa16(stage + OFF_AHI + so, g_xa_hi + (size_t)(b0 + row) * D_SZ + gk);
        cpa16(stage + OFF_ALO + so, g_xa_lo + (size_t)(b0 + row) * D_SZ + gk);
        cpa16(stage + OFF_BHI + so, g_w_hi  + (size_t)(c0 + row) * D_SZ + gk);
        cpa16(stage + OFF_BLO + so, g_w_lo  + (size_t)(c0 + row) * D_SZ + gk);
    }
    CP_COMMIT();
}

__global__ void __launch_bounds__(256, 1) gemm_mma_kernel(float* __restrict__ out) {
    extern __shared__ char smem[];
    uint32_t sb = smem_u32(smem);
    __shared__ float sw_winv[128];

    int tid = threadIdx.x, lane = tid & 31, warp = tid >> 5;
    int warp_m = warp >> 2;        // 0..1  (64 rows each)
    int warp_n = warp & 3;         // 0..3  (32 cols each)
    int b0 = blockIdx.x * 128;
    int c0 = blockIdx.y * 128;

    if (tid < 128) sw_winv[tid] = g_winv[c0 + tid];

    float acc[4][4][4];
#pragma unroll
    for (int mi = 0; mi < 4; ++mi)
#pragma unroll
        for (int ni = 0; ni < 4; ++ni)
#pragma unroll
            for (int q = 0; q < 4; ++q) acc[mi][ni][q] = 0.0f;

    // lane-derived ldmatrix row offsets
    int arow = (lane & 7) + ((lane >> 3) & 1) * 8;
    int aseg = lane >> 4;                                   // 0/1 -> +16B
    uint32_t a_off = (uint32_t)((warp_m * 64 + arow) * PITCH + aseg * 16);
    int brow = (lane & 7) + (lane >> 4) * 8;
    int bseg = (lane >> 3) & 1;
    uint32_t b_off = (uint32_t)((warp_n * 32 + brow) * PITCH + bseg * 16);

    load_chunk(sb + 0,            0, b0, c0, tid);
    load_chunk(sb + STAGE_BYTES,  1, b0, c0, tid);

#pragma unroll
    for (int kc = 0; kc < 8; ++kc) {
        if (kc < 7) { CP_WAIT(1); } else { CP_WAIT(0); }
        __syncthreads();
        uint32_t st = sb + (uint32_t)(kc & 1) * STAGE_BYTES;

#pragma unroll
        for (int kk = 0; kk < 2; ++kk) {
            uint32_t koff = (uint32_t)(kk * 32);
            uint32_t af[4][4], bhf[2][4], blf[2][4];
#pragma unroll
            for (int mi = 0; mi < 4; ++mi)
                ldsm_x4(af[mi], st + OFF_AHI + a_off + mi * (16 * PITCH) + koff);
#pragma unroll
            for (int n2 = 0; n2 < 2; ++n2)
                ldsm_x4(bhf[n2], st + OFF_BHI + b_off + n2 * (16 * PITCH) + koff);
#pragma unroll
            for (int n2 = 0; n2 < 2; ++n2)
                ldsm_x4(blf[n2], st + OFF_BLO + b_off + n2 * (16 * PITCH) + koff);

            // pass 0: A_hi x B_hi,  pass 1: A_hi x B_lo
#pragma unroll
            for (int mi = 0; mi < 4; ++mi)
#pragma unroll
                for (int ni = 0; ni < 4; ++ni) {
                    uint32_t bh[2] = { bhf[ni >> 1][(ni & 1) * 2], bhf[ni >> 1][(ni & 1) * 2 + 1] };
                    mma16816(acc[mi][ni], af[mi], bh);
                    uint32_t bl[2] = { blf[ni >> 1][(ni & 1) * 2], blf[ni >> 1][(ni & 1) * 2 + 1] };
                    mma16816(acc[mi][ni], af[mi], bl);
                }

            // pass 2: A_lo x B_hi
#pragma unroll
            for (int mi = 0; mi < 4; ++mi)
                ldsm_x4(af[mi], st + OFF_ALO + a_off + mi * (16 * PITCH) + koff);
#pragma unroll
            for (int mi = 0; mi < 4; ++mi)
#pragma unroll
                for (int ni = 0; ni < 4; ++ni) {
                    uint32_t bh[2] = { bhf[ni >> 1][(ni & 1) * 2], bhf[ni >> 1][(ni & 1) * 2 + 1] };
                    mma16816(acc[mi][ni], af[mi], bh);
                }
        }
        __syncthreads();
        if (kc < 6) load_chunk(sb + (uint32_t)(kc & 1) * STAGE_BYTES, kc + 2, b0, c0, tid);
    }

    // epilogue: scale by winv, write predicts (guard C_SZ edge)
    int rbase = warp_m * 64 + (lane >> 2);
    int ncol2 = 2 * (lane & 3);
#pragma unroll
    for (int mi = 0; mi < 4; ++mi) {
#pragma unroll
        for (int ni = 0; ni < 4; ++ni) {
            int n_local = warp_n * 32 + ni * 8 + ncol2;
            int n_glob  = c0 + n_local;
            if (n_glob >= C_SZ) continue;
            float w0 = sw_winv[n_local], w1 = sw_winv[n_local + 1];
            int m0 = b0 + rbase + mi * 16;
            float2 v0 = make_float2(acc[mi][ni][0] * w0, acc[mi][ni][1] * w1);
            float2 v1 = make_float2(acc[mi][ni][2] * w0, acc[mi][ni][3] * w1);
            *(float2*)(out + (size_t)m0 * C_SZ + n_glob)       = v0;
            *(float2*)(out + (size_t)(m0 + 8) * C_SZ + n_glob) = v1;
        }
    }
}

// ---------------------------------------------------------------------------
extern "C" void kernel_launch(void* const* d_in, const int* in_sizes, int n_in,
                              void* d_out, int out_size) {
    const float* x   = (const float*)d_in[0];
    const int*   tgt = (const int*)d_in[1];
    const float* w   = (const float*)d_in[2];
    float* out = (float*)d_out;

    static bool attr_set = false;
    if (!attr_set) {
        cudaFuncSetAttribute(gemm_mma_kernel, cudaFuncAttributeMaxDynamicSharedMemorySize, SMEM_GEMM);
        attr_set = true;
    }

    normalize_x_kernel<<<B_SZ, 256>>>(x);
    winv_kernel<<<(C_PAD * 32 + 255) / 256, 256>>>(w);
    convert_w_kernel<<<(int)(((size_t)C_PAD * D_SZ / 8 + 255) / 256), 256>>>(w);
    copy_w_kernel<<<(C_SZ * D_SZ / 4 + 255) / 256, 256>>>(w, out + OUT_W);
    targets_out_kernel<<<(B_SZ + 255) / 256, 256>>>(tgt, out + OUT_TGT);
    seq_update_kernel<<<B_SZ, 256>>>(tgt, out + OUT_W);

    dim3 grid(B_SZ / 128, C_PAD / 128);   // (8, 782); x fastest -> CTAs sharing B tile run together
    gemm_mma_kernel<<<grid, 256, SMEM_GEMM>>>(out + OUT_PRED);
}